// round 4
// baseline (speedup 1.0000x reference)
#include <cuda_runtime.h>
#include <math.h>

#define B   8
#define C   64
#define NP  65536
#define RR  32
#define R3  32768   // 32^3

// Scratch (device globals — no allocation allowed in kernel_launch)
__device__ float g_scratch[(size_t)B * R3 * C];   // [B][R3][C]  channel-contiguous for v4 atomics
__device__ float g_cnt[B * R3];                   // per-voxel point counts
__device__ int   g_flat[B * NP];                  // per-point flat voxel id
__device__ float g_stats[B * 4];                  // meanx, meany, meanz, denom

// ---------------------------------------------------------------------------
// K1: per-batch stats — mean over N, then max L2 norm of centered coords.
// One block per batch, two-phase shared reduction.
// ---------------------------------------------------------------------------
__global__ void stats_kernel(const float* __restrict__ coords) {
    const int b = blockIdx.x;
    const int t = threadIdx.x;
    const float* cb = coords + (size_t)b * 3 * NP;

    __shared__ float shx[1024], shy[1024], shz[1024];
    __shared__ float mean[3];

    float sx = 0.f, sy = 0.f, sz = 0.f;
    for (int i = t; i < NP; i += 1024) {
        sx += cb[i];
        sy += cb[NP + i];
        sz += cb[2 * NP + i];
    }
    shx[t] = sx; shy[t] = sy; shz[t] = sz;
    __syncthreads();
    for (int s = 512; s > 0; s >>= 1) {
        if (t < s) { shx[t] += shx[t + s]; shy[t] += shy[t + s]; shz[t] += shz[t + s]; }
        __syncthreads();
    }
    if (t == 0) {
        mean[0] = shx[0] / (float)NP;
        mean[1] = shy[0] / (float)NP;
        mean[2] = shz[0] / (float)NP;
    }
    __syncthreads();

    const float mx = mean[0], my = mean[1], mz = mean[2];
    float mmax = 0.f;
    for (int i = t; i < NP; i += 1024) {
        float x = cb[i]          - mx;
        float y = cb[NP + i]     - my;
        float z = cb[2 * NP + i] - mz;
        float sq = x * x + y * y + z * z;
        mmax = fmaxf(mmax, sq);
    }
    shx[t] = mmax;
    __syncthreads();
    for (int s = 512; s > 0; s >>= 1) {
        if (t < s) shx[t] = fmaxf(shx[t], shx[t + s]);
        __syncthreads();
    }
    if (t == 0) {
        g_stats[b * 4 + 0] = mx;
        g_stats[b * 4 + 1] = my;
        g_stats[b * 4 + 2] = mz;
        // max(norm) == sqrt(max(sq)) (sqrt monotone, correctly rounded); EPS = 0
        g_stats[b * 4 + 3] = 2.0f * sqrtf(shx[0]);
    }
}

// ---------------------------------------------------------------------------
// K2: per-point — compute nc (output), flat voxel id, and voxel counts.
// ---------------------------------------------------------------------------
__global__ void points_kernel(const float* __restrict__ coords,
                              float* __restrict__ nc_out) {
    const int idx = blockIdx.x * blockDim.x + threadIdx.x;
    if (idx >= B * NP) return;
    const int b = idx >> 16;
    const int n = idx & (NP - 1);

    const float* cb = coords + (size_t)b * 3 * NP;
    const float mx    = g_stats[b * 4 + 0];
    const float my    = g_stats[b * 4 + 1];
    const float mz    = g_stats[b * 4 + 2];
    const float denom = g_stats[b * 4 + 3];

    float x = ((cb[n]          - mx) / denom + 0.5f) * (float)RR;
    float y = ((cb[NP + n]     - my) / denom + 0.5f) * (float)RR;
    float z = ((cb[2 * NP + n] - mz) / denom + 0.5f) * (float)RR;
    x = fminf(fmaxf(x, 0.0f), (float)(RR - 1));
    y = fminf(fmaxf(y, 0.0f), (float)(RR - 1));
    z = fminf(fmaxf(z, 0.0f), (float)(RR - 1));

    float* nb = nc_out + (size_t)b * 3 * NP;
    nb[n]          = x;
    nb[NP + n]     = y;
    nb[2 * NP + n] = z;

    // jnp.round == round-half-to-even == rintf
    const int vx = (int)rintf(x);
    const int vy = (int)rintf(y);
    const int vz = (int)rintf(z);
    const int flat = (vx * RR + vy) * RR + vz;

    g_flat[idx] = flat;
    atomicAdd(&g_cnt[b * R3 + flat], 1.0f);
}

// ---------------------------------------------------------------------------
// K3: feature scatter. One thread per point; loop over 16 channel-quads.
// Loads are warp-coalesced (lane = point index). Accumulation via
// red.global.add.v4.f32 into channel-contiguous scratch (16B-aligned).
// ---------------------------------------------------------------------------
__global__ void scatter_kernel(const float* __restrict__ features) {
    const int idx = blockIdx.x * blockDim.x + threadIdx.x;
    if (idx >= B * NP) return;
    const int b = idx >> 16;
    const int n = idx & (NP - 1);
    const int flat = g_flat[idx];

    const float* f = features + (size_t)b * C * NP + n;
    float* dst = g_scratch + ((size_t)b * R3 + flat) * C;

#pragma unroll
    for (int cq = 0; cq < C / 4; cq++) {
        float v0 = f[(size_t)(4 * cq + 0) * NP];
        float v1 = f[(size_t)(4 * cq + 1) * NP];
        float v2 = f[(size_t)(4 * cq + 2) * NP];
        float v3 = f[(size_t)(4 * cq + 3) * NP];
        asm volatile("red.global.add.v4.f32 [%0], {%1, %2, %3, %4};"
                     :: "l"(dst + 4 * cq), "f"(v0), "f"(v1), "f"(v2), "f"(v3)
                     : "memory");
    }
}

// ---------------------------------------------------------------------------
// K4: normalize by count + transpose [B][R3][C] -> [B][C][R3].
// Block = 32 voxels x 64 channels tile through padded smem (conflict-free).
// ---------------------------------------------------------------------------
__global__ void finalize_kernel(float* __restrict__ out) {
    const int blk = blockIdx.x;           // B * (R3/32) blocks
    const int b  = blk >> 10;             // R3/32 = 1024
    const int v0 = (blk & 1023) * 32;
    const int t  = threadIdx.x;           // 256 threads

    __shared__ float tile[32][C + 1];
    __shared__ float inv[32];

    const float* src = g_scratch + ((size_t)b * R3 + v0) * C;
    for (int i = t; i < 32 * C; i += 256) {
        tile[i >> 6][i & 63] = src[i];    // consecutive threads -> consecutive c: coalesced
    }
    if (t < 32) inv[t] = 1.0f / fmaxf(g_cnt[b * R3 + v0 + t], 1.0f);
    __syncthreads();

    float* dst = out + (size_t)b * C * R3 + v0;
    for (int j = t; j < 32 * C; j += 256) {
        const int c = j >> 5, v = j & 31; // consecutive threads -> consecutive v: coalesced
        dst[(size_t)c * R3 + v] = tile[v][c] * inv[v];
    }
}

// ---------------------------------------------------------------------------
extern "C" void kernel_launch(void* const* d_in, const int* in_sizes, int n_in,
                              void* d_out, int out_size) {
    // Identify inputs by size (features: 33,554,432 elems; coords: 1,572,864)
    const float* features = (const float*)d_in[0];
    const float* coords   = (const float*)d_in[1];
    if (n_in >= 2 && in_sizes[0] < in_sizes[1]) {
        features = (const float*)d_in[1];
        coords   = (const float*)d_in[0];
    }

    float* out    = (float*)d_out;
    float* nc_out = out + (size_t)B * C * R3;   // nc follows vox_feat in d_out

    void *pScratch = nullptr, *pCnt = nullptr;
    cudaGetSymbolAddress(&pScratch, g_scratch);
    cudaGetSymbolAddress(&pCnt, g_cnt);
    cudaMemsetAsync(pScratch, 0, sizeof(float) * (size_t)B * R3 * C);
    cudaMemsetAsync(pCnt,     0, sizeof(float) * (size_t)B * R3);

    stats_kernel<<<B, 1024>>>(coords);
    points_kernel<<<(B * NP) / 256, 256>>>(coords, nc_out);
    scatter_kernel<<<(B * NP) / 256, 256>>>(features);
    finalize_kernel<<<(B * R3) / 32, 256>>>(out);
}

// round 5
// speedup vs baseline: 1.5913x; 1.5913x over previous
#include <cuda_runtime.h>
#include <math.h>

#define B   8
#define C   64
#define NP  65536
#define RR  32
#define R3  32768   // 32^3

// Scratch (device globals — no allocation allowed in kernel_launch)
__device__ float g_scratch[(size_t)B * R3 * C];   // [B][R3][C]  channel-contiguous
__device__ float g_cnt[B * R3];                   // per-voxel point counts
__device__ int   g_flat[B * NP];                  // per-point flat voxel id
__device__ float g_stats[B * 4];                  // meanx, meany, meanz, maxsq(bits)
__device__ float g_part[B * 32 * 3];              // partial sums for mean

// ---------------------------------------------------------------------------
// K1a: partial sums for mean. 32 chunks per batch, deterministic tree.
// ---------------------------------------------------------------------------
__global__ void sum_part_kernel(const float* __restrict__ coords) {
    const int b     = blockIdx.x >> 5;
    const int chunk = blockIdx.x & 31;
    const int t     = threadIdx.x;            // 256
    const int base  = chunk * 2048;
    const float* cb = coords + (size_t)b * 3 * NP;

    float sx = 0.f, sy = 0.f, sz = 0.f;
#pragma unroll
    for (int k = 0; k < 8; k++) {
        int i = base + t + k * 256;
        sx += cb[i];
        sy += cb[NP + i];
        sz += cb[2 * NP + i];
    }
#pragma unroll
    for (int s = 16; s > 0; s >>= 1) {
        sx += __shfl_down_sync(0xFFFFFFFFu, sx, s);
        sy += __shfl_down_sync(0xFFFFFFFFu, sy, s);
        sz += __shfl_down_sync(0xFFFFFFFFu, sz, s);
    }
    __shared__ float wx[8], wy[8], wz[8];
    if ((t & 31) == 0) { wx[t >> 5] = sx; wy[t >> 5] = sy; wz[t >> 5] = sz; }
    __syncthreads();
    if (t == 0) {
        float ax = 0.f, ay = 0.f, az = 0.f;
#pragma unroll
        for (int w = 0; w < 8; w++) { ax += wx[w]; ay += wy[w]; az += wz[w]; }
        float* p = g_part + ((size_t)b * 32 + chunk) * 3;
        p[0] = ax; p[1] = ay; p[2] = az;
    }
}

// K1b: combine 32 partials -> mean. grid 8, block 96 (3 warps, one per comp).
__global__ void sum_combine_kernel() {
    const int b = blockIdx.x;
    const int t = threadIdx.x;                // 96
    const int comp = t >> 5;
    const int j    = t & 31;
    float v = g_part[((size_t)b * 32 + j) * 3 + comp];
#pragma unroll
    for (int s = 16; s > 0; s >>= 1)
        v += __shfl_down_sync(0xFFFFFFFFu, v, s);
    if (j == 0) g_stats[b * 4 + comp] = v / (float)NP;
}

// K1c: max squared norm of centered coords. atomicMax on float bits (>=0) is
// order-independent -> deterministic.
__global__ void maxsq_kernel(const float* __restrict__ coords) {
    const int b     = blockIdx.x >> 5;
    const int chunk = blockIdx.x & 31;
    const int t     = threadIdx.x;            // 256
    const int base  = chunk * 2048;
    const float* cb = coords + (size_t)b * 3 * NP;
    const float mx = g_stats[b * 4 + 0];
    const float my = g_stats[b * 4 + 1];
    const float mz = g_stats[b * 4 + 2];

    float m = 0.f;
#pragma unroll
    for (int k = 0; k < 8; k++) {
        int i = base + t + k * 256;
        float x = cb[i]          - mx;
        float y = cb[NP + i]     - my;
        float z = cb[2 * NP + i] - mz;
        m = fmaxf(m, x * x + y * y + z * z);
    }
#pragma unroll
    for (int s = 16; s > 0; s >>= 1)
        m = fmaxf(m, __shfl_down_sync(0xFFFFFFFFu, m, s));
    __shared__ float wm[8];
    if ((t & 31) == 0) wm[t >> 5] = m;
    __syncthreads();
    if (t == 0) {
#pragma unroll
        for (int w = 1; w < 8; w++) m = fmaxf(m, wm[w]);
        atomicMax((unsigned*)&g_stats[b * 4 + 3], __float_as_uint(m));
    }
}

// ---------------------------------------------------------------------------
// K2: per-point — nc (output), flat voxel id, voxel counts.
// ---------------------------------------------------------------------------
__global__ void points_kernel(const float* __restrict__ coords,
                              float* __restrict__ nc_out) {
    const int idx = blockIdx.x * blockDim.x + threadIdx.x;
    const int b = idx >> 16;
    const int n = idx & (NP - 1);

    const float* cb = coords + (size_t)b * 3 * NP;
    const float mx = g_stats[b * 4 + 0];
    const float my = g_stats[b * 4 + 1];
    const float mz = g_stats[b * 4 + 2];
    const float denom = 2.0f * sqrtf(g_stats[b * 4 + 3]);   // EPS = 0

    float x = ((cb[n]          - mx) / denom + 0.5f) * (float)RR;
    float y = ((cb[NP + n]     - my) / denom + 0.5f) * (float)RR;
    float z = ((cb[2 * NP + n] - mz) / denom + 0.5f) * (float)RR;
    x = fminf(fmaxf(x, 0.0f), (float)(RR - 1));
    y = fminf(fmaxf(y, 0.0f), (float)(RR - 1));
    z = fminf(fmaxf(z, 0.0f), (float)(RR - 1));

    float* nb = nc_out + (size_t)b * 3 * NP;
    nb[n]          = x;
    nb[NP + n]     = y;
    nb[2 * NP + n] = z;

    // jnp.round == round-half-to-even == rintf
    const int vx = (int)rintf(x);
    const int vy = (int)rintf(y);
    const int vz = (int)rintf(z);
    const int flat = (vx * RR + vy) * RR + vz;

    g_flat[idx] = flat;
    atomicAdd(&g_cnt[b * R3 + flat], 1.0f);
}

// ---------------------------------------------------------------------------
// K3: feature scatter, line-coalesced atomics.
// Phase 1: coalesced loads (lane = point), stage 128-pt x 64-ch tile in smem
//          (row stride 68 floats -> STS.128/LDS.128 conflict-free in 16B groups).
// Phase 2: each warp processes point PAIRS: lanes 0-15 cover all 64 channels
//          (256B contiguous) of point A, lanes 16-31 of point B. One red.v4
//          instruction touches only 4 cache lines instead of 32.
// ---------------------------------------------------------------------------
#define TPTS 128           // points per block
#define TSTR 68            // smem row stride in floats (272B = 17*16B)

__global__ __launch_bounds__(256) void scatter_kernel(const float* __restrict__ features) {
    const int blk = blockIdx.x;               // B * NP / TPTS = 4096
    const int b   = blk >> 9;                 // 512 blocks per batch
    const int n0  = (blk & 511) * TPTS;
    const int t   = threadIdx.x;              // 256

    __shared__ __align__(16) float tile[TPTS * TSTR];
    __shared__ int sflat[TPTS];

    // ---- Phase 1: load + transpose into smem ----
    {
        const int p  = t & (TPTS - 1);        // point within tile
        const int ch = (t >> 7) * 8;          // channel-quad base: 0 or 8
        const float* f = features + (size_t)b * C * NP + n0 + p;
#pragma unroll
        for (int q = 0; q < 8; q++) {
            const int c = (ch + q) * 4;
            float4 v;
            v.x = __ldg(f + (size_t)(c + 0) * NP);
            v.y = __ldg(f + (size_t)(c + 1) * NP);
            v.z = __ldg(f + (size_t)(c + 2) * NP);
            v.w = __ldg(f + (size_t)(c + 3) * NP);
            *(float4*)&tile[p * TSTR + c] = v;
        }
        if (t < TPTS) sflat[t] = g_flat[b * NP + n0 + t];
    }
    __syncthreads();

    // ---- Phase 2: coalesced-lane reds ----
    {
        const int w    = t >> 5;              // warp 0..7, 16 points each
        const int l    = t & 31;
        const int half = l >> 4;              // 0 -> point A, 1 -> point B
        const int lc   = (l & 15) * 4;        // channel offset
        float* sbase = g_scratch + (size_t)b * R3 * C;
#pragma unroll
        for (int i = 0; i < 8; i++) {
            const int p = w * 16 + 2 * i + half;
            const int flat = sflat[p];
            const float4 v = *(const float4*)&tile[p * TSTR + lc];
            float* dst = sbase + (size_t)flat * C + lc;
            asm volatile("red.global.add.v4.f32 [%0], {%1, %2, %3, %4};"
                         :: "l"(dst), "f"(v.x), "f"(v.y), "f"(v.z), "f"(v.w)
                         : "memory");
        }
    }
}

// ---------------------------------------------------------------------------
// K4: normalize by count + transpose [B][R3][C] -> [B][C][R3].
// 64-voxel tile, float4 global loads/stores, stride-65 smem (<=2-way conflicts).
// ---------------------------------------------------------------------------
__global__ __launch_bounds__(256) void finalize_kernel(float* __restrict__ out) {
    const int blk = blockIdx.x;               // B * R3 / 64 = 4096
    const int b   = blk >> 9;                 // 512 blocks per batch
    const int v0  = (blk & 511) * 64;
    const int t   = threadIdx.x;              // 256

    __shared__ float tile[64 * 65];
    __shared__ float inv[64];

    const float4* src = (const float4*)(g_scratch + ((size_t)b * R3 + v0) * C);
#pragma unroll
    for (int it = 0; it < 4; it++) {
        const int i = t + it * 256;           // float4 index (1024 total)
        const float4 u = src[i];
        const int g = i * 4;
        const int v = g >> 6, c = g & 63;
        tile[v * 65 + c + 0] = u.x;
        tile[v * 65 + c + 1] = u.y;
        tile[v * 65 + c + 2] = u.z;
        tile[v * 65 + c + 3] = u.w;
    }
    if (t < 64) inv[t] = 1.0f / fmaxf(g_cnt[b * R3 + v0 + t], 1.0f);
    __syncthreads();

    float* dst = out + (size_t)b * C * R3 + v0;
#pragma unroll
    for (int it = 0; it < 4; it++) {
        const int i = t + it * 256;
        const int g = i * 4;
        const int c = g >> 6, v = g & 63;
        float4 r;
        r.x = tile[(v + 0) * 65 + c] * inv[v + 0];
        r.y = tile[(v + 1) * 65 + c] * inv[v + 1];
        r.z = tile[(v + 2) * 65 + c] * inv[v + 2];
        r.w = tile[(v + 3) * 65 + c] * inv[v + 3];
        *(float4*)&dst[(size_t)c * R3 + v] = r;
    }
}

// ---------------------------------------------------------------------------
extern "C" void kernel_launch(void* const* d_in, const int* in_sizes, int n_in,
                              void* d_out, int out_size) {
    const float* features = (const float*)d_in[0];
    const float* coords   = (const float*)d_in[1];
    if (n_in >= 2 && in_sizes[0] < in_sizes[1]) {
        features = (const float*)d_in[1];
        coords   = (const float*)d_in[0];
    }

    float* out    = (float*)d_out;
    float* nc_out = out + (size_t)B * C * R3;   // nc follows vox_feat in d_out

    void *pScratch = nullptr, *pCnt = nullptr, *pStats = nullptr;
    cudaGetSymbolAddress(&pScratch, g_scratch);
    cudaGetSymbolAddress(&pCnt, g_cnt);
    cudaGetSymbolAddress(&pStats, g_stats);
    cudaMemsetAsync(pScratch, 0, sizeof(float) * (size_t)B * R3 * C);
    cudaMemsetAsync(pCnt,     0, sizeof(float) * (size_t)B * R3);
    cudaMemsetAsync(pStats,   0, sizeof(float) * (size_t)B * 4);

    sum_part_kernel<<<B * 32, 256>>>(coords);
    sum_combine_kernel<<<B, 96>>>();
    maxsq_kernel<<<B * 32, 256>>>(coords);
    points_kernel<<<(B * NP) / 256, 256>>>(coords, nc_out);
    scatter_kernel<<<(B * NP) / TPTS, 256>>>(features);
    finalize_kernel<<<(B * R3) / 64, 256>>>(out);
}